// round 3
// baseline (speedup 1.0000x reference)
#include <cuda_runtime.h>
#include <cuda_bf16.h>

// Problem constants (fixed by the reference)
#define B_ 32
#define D_ 64
#define T_ 4096
#define K_ 512
#define N_ (B_ * T_)        // 131072 tokens
#define NQ_ (B_ * D_ * T_)  // 8388608 quantized elements

// Scratch (device globals: no allocation allowed)
__device__ int          g_idx[N_];
__device__ float        g_cbnorm[K_];
__device__ float        g_partial[B_ * D_];
__device__ unsigned int g_count;
__device__ unsigned int g_maxe_bits;   // max |codebook element| as float bits (>=0)

// ---------------------------------------------------------------------------
// helpers
// ---------------------------------------------------------------------------
__device__ __forceinline__ unsigned bf16x2_of(float lo, float hi) {
    unsigned r;
    asm("cvt.rn.bf16x2.f32 %0, %1, %2;" : "=r"(r) : "f"(hi), "f"(lo));
    return r;
}

__device__ __forceinline__ void mma_bf16(float& d0, float& d1, float& d2, float& d3,
                                         unsigned a0, unsigned a1, unsigned a2, unsigned a3,
                                         unsigned b0, unsigned b1) {
    asm("mma.sync.aligned.m16n8k16.row.col.f32.bf16.bf16.f32 "
        "{%0,%1,%2,%3}, {%4,%5,%6,%7}, {%8,%9}, {%0,%1,%2,%3};"
        : "+f"(d0), "+f"(d1), "+f"(d2), "+f"(d3)
        : "r"(a0), "r"(a1), "r"(a2), "r"(a3), "r"(b0), "r"(b1));
}

// Exact fp32 distance, bit-identical to the round-0 kernel (rel_err = 0.0):
// dist = fl( fl(A + cn[k]) - fl(2 * dot) ), dot via 4 stride-4 chains.
__device__ __forceinline__ float exact_dist(const float* zr, float A,
                                            const float* __restrict__ cb,
                                            const float* cn, int k) {
    const float4* cp = reinterpret_cast<const float4*>(cb + (size_t)k * D_);
    float s0 = 0.f, s1 = 0.f, s2 = 0.f, s3 = 0.f;
#pragma unroll
    for (int i = 0; i < 16; ++i) {
        float4 c = __ldg(cp + i);
        s0 = fmaf(zr[4 * i + 0], c.x, s0);
        s1 = fmaf(zr[4 * i + 1], c.y, s1);
        s2 = fmaf(zr[4 * i + 2], c.z, s2);
        s3 = fmaf(zr[4 * i + 3], c.w, s3);
    }
    float dot = __fadd_rn(__fadd_rn(s0, s1), __fadd_rn(s2, s3));
    return __fadd_rn(__fadd_rn(A, cn[k]), -__fmul_rn(2.0f, dot));
}

// ---------------------------------------------------------------------------
// Kernel 0: codebook row norms ||e_k||^2 (sequential fmaf, round-0 order)
// plus chip-wide max |e| for the sound pruning margin.
// ---------------------------------------------------------------------------
__global__ void prep_kernel(const float* __restrict__ cb) {
    int k = blockIdx.x * blockDim.x + threadIdx.x;
    if (k < K_) {
        const float* r = cb + k * D_;
        float a = 0.0f;
        float mx = 0.0f;
#pragma unroll
        for (int i = 0; i < D_; ++i) {
            a = fmaf(r[i], r[i], a);
            mx = fmaxf(mx, fabsf(r[i]));
        }
        g_cbnorm[k] = a;
        atomicMax(&g_maxe_bits, __float_as_uint(mx));  // mx >= 0: bits monotone
    }
}

// ---------------------------------------------------------------------------
// Kernel 1: tensor-core (HMMA bf16) approximate scoring + sound prune +
// exact fp32 rescore. 8 warps/block, 16 tokens/warp, 128 tokens/block.
//
// approx score val_k = fl(cn[k] - 2*dot_bf16) (A constant per token, dropped).
// Candidate set: { k : val_k <= min_val + margin_tok }, margin_tok sound
// w.r.t. bf16 quantization of both operands. Exact rescore decides.
// ---------------------------------------------------------------------------
#define CBH_ROW_BYTES 144            // 72 bf16 per row (conflict-free banks)
#define SM_CBH   0
#define SM_CN    (K_ * CBH_ROW_BYTES)            // 73728
#define SM_CAND  (SM_CN + K_ * 4)                // 75776
#define SM_CCNT  (SM_CAND + 128 * 8 * 4)         // 79872
#define SM_TOTAL (SM_CCNT + 128 * 4)             // 80384
#define CAND_CAP 8

__global__ __launch_bounds__(256)
void argmin_mma_kernel(const float* __restrict__ z,
                       const float* __restrict__ cb,
                       float* __restrict__ out_idx /* may be null */) {
    extern __shared__ char sm[];
    float* cn   = reinterpret_cast<float*>(sm + SM_CN);
    int*   cand = reinterpret_cast<int*>(sm + SM_CAND);
    int*   ccnt = reinterpret_cast<int*>(sm + SM_CCNT);

    const int tid  = threadIdx.x;
    const int lane = tid & 31;
    const int w    = tid >> 5;       // warp 0..7
    const int q    = lane & 3;
    const int g    = lane >> 2;

    const int b    = blockIdx.x >> 5;            // 32 blocks per batch
    const int t0b  = (blockIdx.x & 31) << 7;     // 128 tokens per block

    // ---- stage bf16 codebook (padded rows) + cn, zero counters ----
    for (int i = tid; i < K_ * D_; i += 256) {
        int r = i >> 6, c = i & 63;
        unsigned short h = __bfloat16_as_ushort(__float2bfloat16_rn(cb[i]));
        *reinterpret_cast<unsigned short*>(sm + SM_CBH + r * CBH_ROW_BYTES + c * 2) = h;
    }
    for (int i = tid; i < K_; i += 256) cn[i] = g_cbnorm[i];
    if (tid < 128) ccnt[tid] = 0;
    __syncthreads();

    // ---- A fragments (z, bf16) for this warp's 16 tokens; also sum|z| ----
    const float* zb = z + (size_t)b * (D_ * T_);
    const int tA = t0b + (w << 4) + g;   // token row g
    const int tB = tA + 8;               // token row g+8

    unsigned af[4][4];
    float sabsA = 0.f, sabsB = 0.f;
#pragma unroll
    for (int kc = 0; kc < 4; ++kc) {
        int d0 = kc * 16 + q * 2;
        float x0 = zb[(d0    ) * T_ + tA], x1 = zb[(d0 + 1) * T_ + tA];
        float x2 = zb[(d0 + 8) * T_ + tA], x3 = zb[(d0 + 9) * T_ + tA];
        float y0 = zb[(d0    ) * T_ + tB], y1 = zb[(d0 + 1) * T_ + tB];
        float y2 = zb[(d0 + 8) * T_ + tB], y3 = zb[(d0 + 9) * T_ + tB];
        af[kc][0] = bf16x2_of(x0, x1);
        af[kc][1] = bf16x2_of(y0, y1);
        af[kc][2] = bf16x2_of(x2, x3);
        af[kc][3] = bf16x2_of(y2, y3);
        sabsA += fabsf(x0) + fabsf(x1) + fabsf(x2) + fabsf(x3);
        sabsB += fabsf(y0) + fabsf(y1) + fabsf(y2) + fabsf(y3);
    }
    sabsA += __shfl_xor_sync(0xffffffffu, sabsA, 1);
    sabsA += __shfl_xor_sync(0xffffffffu, sabsA, 2);
    sabsB += __shfl_xor_sync(0xffffffffu, sabsB, 1);
    sabsB += __shfl_xor_sync(0xffffffffu, sabsB, 2);

    // sound margin: thresh = min + 1.5 * 2^-6 * maxe * sum|z|  (+ tiny abs eps)
    const float maxe = __uint_as_float(g_maxe_bits);
    const float marginA = 0.0234375f * maxe * sabsA + 1e-7f;
    const float marginB = 0.0234375f * maxe * sabsB + 1e-7f;

    // ---- pass 1: approximate min per token ----
    float minA = 3.402823466e38f, minB = 3.402823466e38f;
#pragma unroll 4
    for (int nt = 0; nt < 64; ++nt) {
        const int nb = nt * 8;
        const char* brow = sm + SM_CBH + (nb + g) * CBH_ROW_BYTES;
        float d0 = 0.f, d1 = 0.f, d2 = 0.f, d3 = 0.f;
#pragma unroll
        for (int kc = 0; kc < 4; ++kc) {
            unsigned b0 = *reinterpret_cast<const unsigned*>(brow + (kc * 16 + q * 2) * 2);
            unsigned b1 = *reinterpret_cast<const unsigned*>(brow + (kc * 16 + q * 2 + 8) * 2);
            mma_bf16(d0, d1, d2, d3, af[kc][0], af[kc][1], af[kc][2], af[kc][3], b0, b1);
        }
        const int c0 = nb + q * 2;
        float cn0 = cn[c0], cn1 = cn[c0 + 1];
        float v0 = fmaf(-2.f, d0, cn0), v1 = fmaf(-2.f, d1, cn1);
        float v2 = fmaf(-2.f, d2, cn0), v3 = fmaf(-2.f, d3, cn1);
        minA = fminf(minA, fminf(v0, v1));
        minB = fminf(minB, fminf(v2, v3));
    }
    minA = fminf(minA, __shfl_xor_sync(0xffffffffu, minA, 1));
    minA = fminf(minA, __shfl_xor_sync(0xffffffffu, minA, 2));
    minB = fminf(minB, __shfl_xor_sync(0xffffffffu, minB, 1));
    minB = fminf(minB, __shfl_xor_sync(0xffffffffu, minB, 2));
    const float thA = minA + marginA;
    const float thB = minB + marginB;

    // ---- pass 2: flag candidates within margin ----
    const int tlA = (w << 4) + g;
    const int tlB = tlA + 8;
#pragma unroll 4
    for (int nt = 0; nt < 64; ++nt) {
        const int nb = nt * 8;
        const char* brow = sm + SM_CBH + (nb + g) * CBH_ROW_BYTES;
        float d0 = 0.f, d1 = 0.f, d2 = 0.f, d3 = 0.f;
#pragma unroll
        for (int kc = 0; kc < 4; ++kc) {
            unsigned b0 = *reinterpret_cast<const unsigned*>(brow + (kc * 16 + q * 2) * 2);
            unsigned b1 = *reinterpret_cast<const unsigned*>(brow + (kc * 16 + q * 2 + 8) * 2);
            mma_bf16(d0, d1, d2, d3, af[kc][0], af[kc][1], af[kc][2], af[kc][3], b0, b1);
        }
        const int c0 = nb + q * 2;
        float cn0 = cn[c0], cn1 = cn[c0 + 1];
        float v0 = fmaf(-2.f, d0, cn0), v1 = fmaf(-2.f, d1, cn1);
        float v2 = fmaf(-2.f, d2, cn0), v3 = fmaf(-2.f, d3, cn1);
        if (v0 <= thA) { int p = atomicAdd(&ccnt[tlA], 1); if (p < CAND_CAP) cand[tlA * CAND_CAP + p] = c0; }
        if (v1 <= thA) { int p = atomicAdd(&ccnt[tlA], 1); if (p < CAND_CAP) cand[tlA * CAND_CAP + p] = c0 + 1; }
        if (v2 <= thB) { int p = atomicAdd(&ccnt[tlB], 1); if (p < CAND_CAP) cand[tlB * CAND_CAP + p] = c0; }
        if (v3 <= thB) { int p = atomicAdd(&ccnt[tlB], 1); if (p < CAND_CAP) cand[tlB * CAND_CAP + p] = c0 + 1; }
    }
    __syncwarp();

    // ---- exact rescore: lanes 0..15, one token each ----
    if (lane < 16) {
        const int tl = (w << 4) + lane;
        const int t  = t0b + tl;
        const int cnt = ccnt[tl];
        int bestk;
        if (cnt == 1) {
            bestk = cand[tl * CAND_CAP];
        } else {
            float zr[D_];
#pragma unroll
            for (int i = 0; i < D_; ++i) zr[i] = zb[i * T_ + t];
            float A = 0.f;
#pragma unroll
            for (int i = 0; i < D_; ++i) A = fmaf(zr[i], zr[i], A);

            float bestd = 3.402823466e38f;
            bestk = 0;
            if (cnt <= CAND_CAP) {
                for (int j = 0; j < cnt; ++j) {
                    int k = cand[tl * CAND_CAP + j];
                    float dd = exact_dist(zr, A, cb, cn, k);
                    if (dd < bestd || (dd == bestd && k < bestk)) { bestd = dd; bestk = k; }
                }
            } else {
                // overflow fallback (vanishingly rare): full exact scan
                for (int k = 0; k < K_; ++k) {
                    float dd = exact_dist(zr, A, cb, cn, k);
                    if (dd < bestd) { bestd = dd; bestk = k; }
                }
            }
        }
        const int n = b * T_ + t;
        g_idx[n] = bestk;
        if (out_idx) out_idx[n] = (float)bestk;
    }
}

// ---------------------------------------------------------------------------
// Kernel 2: gather quantized rows (out = fl(z + fl(q - z))), per-block loss
// partials, fused last-block finalize. One block per (b, d) row.
// ---------------------------------------------------------------------------
__global__ __launch_bounds__(256)
void gather_kernel(const float* __restrict__ z,
                   const float* __restrict__ cb,
                   float* __restrict__ out_q /* may be null */,
                   float* __restrict__ loss_ptr /* may be null */) {
    __shared__ float  s_col[K_];
    __shared__ float  red[256];
    __shared__ bool   s_last;
    __shared__ double rd[256];

    const int tid = threadIdx.x;
    const int blk = blockIdx.x;
    const int b   = blk >> 6;
    const int d   = blk & 63;

    for (int i = tid; i < K_; i += 256) s_col[i] = cb[i * D_ + d];
    __syncthreads();

    const long rowoff = (long)(b * D_ + d) * T_;
    float acc = 0.0f;
#pragma unroll
    for (int j = 0; j < 16; ++j) {
        int t = j * 256 + tid;
        int idx = g_idx[b * T_ + t];
        float q  = s_col[idx];
        float zv = z[rowoff + t];
        float diff = __fsub_rn(q, zv);
        if (out_q) out_q[rowoff + t] = __fadd_rn(zv, diff);
        acc = fmaf(diff, diff, acc);
    }

    red[tid] = acc;
    __syncthreads();
    for (int s = 128; s > 0; s >>= 1) {
        if (tid < s) red[tid] += red[tid + s];
        __syncthreads();
    }
    if (tid == 0) {
        g_partial[blk] = red[0];
        __threadfence();
        unsigned int ticket = atomicAdd(&g_count, 1u);
        s_last = (ticket == (unsigned)(B_ * D_ - 1));
    }
    __syncthreads();

    if (s_last) {
        double s = 0.0;
        for (int i = tid; i < B_ * D_; i += 256) s += (double)g_partial[i];
        rd[tid] = s;
        __syncthreads();
        for (int st = 128; st > 0; st >>= 1) {
            if (tid < st) rd[tid] += rd[tid + st];
            __syncthreads();
        }
        if (tid == 0) {
            if (loss_ptr) {
                float cl = (float)(rd[0] / (double)NQ_);
                loss_ptr[0] = __fadd_rn(cl, __fmul_rn(0.25f, cl));
            }
            g_count = 0;
        }
    }
}

// ---------------------------------------------------------------------------
extern "C" void kernel_launch(void* const* d_in, const int* in_sizes, int n_in,
                              void* d_out, int out_size) {
    const float* z  = nullptr;
    const float* cb = nullptr;
    for (int i = 0; i < n_in; ++i) {
        if (in_sizes[i] == NQ_)          z  = (const float*)d_in[i];
        else if (in_sizes[i] == K_ * D_) cb = (const float*)d_in[i];
    }
    if (!z || !cb) return;

    float* out = (float*)d_out;
    float* loss_ptr = nullptr;
    float* q_ptr    = nullptr;
    float* i_ptr    = nullptr;

    if (out_size == 1 + NQ_ + N_) {
        loss_ptr = out; q_ptr = out + 1; i_ptr = out + 1 + NQ_;
    } else if (out_size == NQ_ + N_) {
        q_ptr = out; i_ptr = out + NQ_;
    } else if (out_size == NQ_) {
        q_ptr = out;
    } else if (out_size == N_) {
        i_ptr = out;
    } else if (out_size == 1) {
        loss_ptr = out;
    } else if (out_size > 1 + NQ_ + N_) {
        loss_ptr = out; q_ptr = out + 1; i_ptr = out + 1 + NQ_;
    }

    static bool attr_done = false;
    if (!attr_done) {
        cudaFuncSetAttribute(argmin_mma_kernel,
                             cudaFuncAttributeMaxDynamicSharedMemorySize,
                             SM_TOTAL);
        attr_done = true;
    }

    prep_kernel<<<2, 256>>>(cb);
    argmin_mma_kernel<<<N_ / 128, 256, SM_TOTAL>>>(z, cb, i_ptr);
    gather_kernel<<<B_ * D_, 256>>>(z, cb, q_ptr, loss_ptr);
}

// round 5
// speedup vs baseline: 1.3313x; 1.3313x over previous
#include <cuda_runtime.h>
#include <cstdint>

// Problem constants (fixed by the reference)
#define B_ 32
#define D_ 64
#define T_ 4096
#define K_ 512
#define N_ (B_ * T_)        // 131072 tokens
#define NQ_ (B_ * D_ * T_)  // 8388608 quantized elements

typedef unsigned long long u64;

// Scratch (device globals: no allocation allowed)
__device__ int          g_idx[N_];
__device__ float        g_cbnorm[K_];
__device__ float        g_partial[B_ * D_];
__device__ unsigned int g_count;
__device__ __align__(16) float g_cbperm[K_ * D_];   // quad-permuted fp32 codebook

// ---------------------------------------------------------------------------
// Packed f32x2 helpers (proven to assemble at this harness's PTX target)
// ---------------------------------------------------------------------------
__device__ __forceinline__ u64 pack2(float lo, float hi) {
    u64 r;
    asm("mov.b64 %0, {%1, %2};" : "=l"(r) : "f"(lo), "f"(hi));
    return r;
}
__device__ __forceinline__ void unpack2(u64 v, float& lo, float& hi) {
    asm("mov.b64 {%0, %1}, %2;" : "=f"(lo), "=f"(hi) : "l"(v));
}
__device__ __forceinline__ void fma2(u64& acc, u64 a, u64 b) {
    asm("fma.rn.f32x2 %0, %1, %2, %0;" : "+l"(acc) : "l"(a), "l"(b));
}

// ---------------------------------------------------------------------------
// prep: codebook norms ||e_k||^2 (canonical sequential fmaf order, proven
// rel_err = 0.0) + quad-permuted fp32 codebook image:
//   quad j stores (c[4j], c[4j+2], c[4j+1], c[4j+3])
// so ulonglong2 loads give ((c4j,c4j+2),(c4j+1,c4j+3)) pre-packed.
// ---------------------------------------------------------------------------
__global__ void prep_kernel(const float* __restrict__ cb) {
    int k = blockIdx.x * blockDim.x + threadIdx.x;
    if (k < K_) {
        const float* r = cb + k * D_;
        float a = 0.0f;
#pragma unroll
        for (int i = 0; i < D_; ++i) a = fmaf(r[i], r[i], a);
        g_cbnorm[k] = a;
        float* o = g_cbperm + k * D_;
#pragma unroll
        for (int j = 0; j < 16; ++j) {
            o[4 * j + 0] = r[4 * j + 0];
            o[4 * j + 1] = r[4 * j + 2];
            o[4 * j + 2] = r[4 * j + 1];
            o[4 * j + 3] = r[4 * j + 3];
        }
    }
}

// ---------------------------------------------------------------------------
// argmin: 512 threads/block, one token/thread, full K=512 exact fp32 scan.
// dist_k = fl( fl(A + cn_k) - fl(2*dot_k) ), dot via 4 canonical stride-4
// chains realized as 2 packed f32x2 accumulators with lanes (s0,s2)/(s1,s3);
// combine fl(fl(s0+s1)+fl(s2+s3)) via one fma2 with multiplier (1,1) (exact).
// dist via fmaf(-2, dot, Acn) == fl(Acn - fl(2 dot)) (2*dot exact scaling).
// Strict '<' keeps the FIRST index on ties (jnp.argmin semantics).
// ---------------------------------------------------------------------------
#define SMEM_CB_BYTES (K_ * D_ * 4)               // 131072
#define SMEM_ARG_TOTAL (SMEM_CB_BYTES + K_ * 4)   // 133120

__global__ __launch_bounds__(512, 1)
void argmin_kernel(const float* __restrict__ z,
                   float* __restrict__ out_idx /* may be null */) {
    extern __shared__ char sm[];
    float* cn_s = reinterpret_cast<float*>(sm + SMEM_CB_BYTES);

    const int tid = threadIdx.x;

    // stage permuted codebook (coalesced float4) + norms
    {
        const float4* src = reinterpret_cast<const float4*>(g_cbperm);
        float4* dst = reinterpret_cast<float4*>(sm);
#pragma unroll 4
        for (int i = tid; i < K_ * 16; i += 512) dst[i] = src[i];
        cn_s[tid] = g_cbnorm[tid];   // tid 0..511 covers K_ exactly
    }

    // token for this thread (each block stays within one batch: 512 | 4096)
    const int n  = blockIdx.x * 512 + tid;
    const float* zc = z + ((size_t)(n >> 12) << 18) + (n & 4095);

    // load z (coalesced), canonical ||z||^2, pack lanes (z4j,z4j+2)/(z4j+1,z4j+3)
    float A = 0.0f;
    u64 zp[32];
#pragma unroll
    for (int j = 0; j < 16; ++j) {
        float z0 = zc[(size_t)(4 * j + 0) << 12];
        float z1 = zc[(size_t)(4 * j + 1) << 12];
        float z2 = zc[(size_t)(4 * j + 2) << 12];
        float z3 = zc[(size_t)(4 * j + 3) << 12];
        A = fmaf(z0, z0, A);
        A = fmaf(z1, z1, A);
        A = fmaf(z2, z2, A);
        A = fmaf(z3, z3, A);
        zp[2 * j]     = pack2(z0, z2);
        zp[2 * j + 1] = pack2(z1, z3);
    }
    __syncthreads();

    const ulonglong2* cq = reinterpret_cast<const ulonglong2*>(sm);
    const u64 ONE2 = pack2(1.0f, 1.0f);

    float best = 3.402823466e38f;
    int   bestk = 0;

#pragma unroll 2
    for (int k = 0; k < K_; ++k) {
        const ulonglong2* cp = cq + k * 16;
        u64 a02 = 0ull, a13 = 0ull;    // lanes = (s0,s2) and (s1,s3)
#pragma unroll
        for (int j = 0; j < 16; ++j) {
            ulonglong2 c = cp[j];      // c.x=(c4j,c4j+2), c.y=(c4j+1,c4j+3)
            fma2(a02, zp[2 * j],     c.x);
            fma2(a13, zp[2 * j + 1], c.y);
        }
        // a13 = a02*1 + a13  -> lanes ( fl(s0+s1), fl(s2+s3) ), exact a*1
        fma2(a13, a02, ONE2);
        float lo, hi;
        unpack2(a13, lo, hi);
        float dot  = __fadd_rn(lo, hi);
        float Acn  = __fadd_rn(A, cn_s[k]);
        float dist = fmaf(-2.0f, dot, Acn);   // == fl(Acn - fl(2*dot))
        if (dist < best) { best = dist; bestk = k; }
    }

    g_idx[n] = bestk;
    if (out_idx) out_idx[n] = (float)bestk;
}

// ---------------------------------------------------------------------------
// gather: out = fl(z + fl(q - z)), per-block loss partials, fused finalize.
// One block per (b, d) row; coalesced over t. (Verbatim from passing round 2.)
// ---------------------------------------------------------------------------
__global__ __launch_bounds__(256)
void gather_kernel(const float* __restrict__ z,
                   const float* __restrict__ cb,
                   float* __restrict__ out_q /* may be null */,
                   float* __restrict__ loss_ptr /* may be null */) {
    __shared__ float  s_col[K_];
    __shared__ float  red[256];
    __shared__ bool   s_last;
    __shared__ double rd[256];

    const int tid = threadIdx.x;
    const int blk = blockIdx.x;
    const int b   = blk >> 6;
    const int d   = blk & 63;

    for (int i = tid; i < K_; i += 256) s_col[i] = cb[i * D_ + d];
    __syncthreads();

    const long rowoff = (long)(b * D_ + d) * T_;
    float acc = 0.0f;
#pragma unroll
    for (int j = 0; j < 16; ++j) {
        int t = j * 256 + tid;
        int idx = g_idx[b * T_ + t];
        float q  = s_col[idx];
        float zv = z[rowoff + t];
        float diff = __fsub_rn(q, zv);
        if (out_q) out_q[rowoff + t] = __fadd_rn(zv, diff);
        acc = fmaf(diff, diff, acc);
    }

    red[tid] = acc;
    __syncthreads();
    for (int s = 128; s > 0; s >>= 1) {
        if (tid < s) red[tid] += red[tid + s];
        __syncthreads();
    }
    if (tid == 0) {
        g_partial[blk] = red[0];
        __threadfence();
        unsigned int ticket = atomicAdd(&g_count, 1u);
        s_last = (ticket == (unsigned)(B_ * D_ - 1));
    }
    __syncthreads();

    if (s_last) {
        double s = 0.0;
        for (int i = tid; i < B_ * D_; i += 256) s += (double)g_partial[i];
        rd[tid] = s;
        __syncthreads();
        for (int st = 128; st > 0; st >>= 1) {
            if (tid < st) rd[tid] += rd[tid + st];
            __syncthreads();
        }
        if (tid == 0) {
            if (loss_ptr) {
                float cl = (float)(rd[0] / (double)NQ_);
                loss_ptr[0] = __fadd_rn(cl, __fmul_rn(0.25f, cl));
            }
            g_count = 0;
        }
    }
}

// ---------------------------------------------------------------------------
extern "C" void kernel_launch(void* const* d_in, const int* in_sizes, int n_in,
                              void* d_out, int out_size) {
    const float* z  = nullptr;
    const float* cb = nullptr;
    for (int i = 0; i < n_in; ++i) {
        if (in_sizes[i] == NQ_)          z  = (const float*)d_in[i];
        else if (in_sizes[i] == K_ * D_) cb = (const float*)d_in[i];
    }
    if (!z || !cb) return;

    float* out = (float*)d_out;
    float* loss_ptr = nullptr;
    float* q_ptr    = nullptr;
    float* i_ptr    = nullptr;

    if (out_size == 1 + NQ_ + N_) {
        loss_ptr = out; q_ptr = out + 1; i_ptr = out + 1 + NQ_;
    } else if (out_size == NQ_ + N_) {
        q_ptr = out; i_ptr = out + NQ_;
    } else if (out_size == NQ_) {
        q_ptr = out;
    } else if (out_size == N_) {
        i_ptr = out;
    } else if (out_size == 1) {
        loss_ptr = out;
    } else if (out_size > 1 + NQ_ + N_) {
        loss_ptr = out; q_ptr = out + 1; i_ptr = out + 1 + NQ_;
    }

    static bool attr_done = false;
    if (!attr_done) {
        cudaFuncSetAttribute(argmin_kernel,
                             cudaFuncAttributeMaxDynamicSharedMemorySize,
                             SMEM_ARG_TOTAL);
        attr_done = true;
    }

    prep_kernel<<<16, 32>>>(cb);
    argmin_kernel<<<N_ / 512, 512, SMEM_ARG_TOTAL>>>(z, i_ptr);
    gather_kernel<<<B_ * D_, 256>>>(z, cb, q_ptr, loss_ptr);
}